// round 16
// baseline (speedup 1.0000x reference)
#include <cuda_runtime.h>
#include <cuda_fp16.h>
#include <stdint.h>
#include <math.h>

#define S_LEN 4096
#define D_MODEL 1024
#define NHEAD 16
#define HDK 64
// Q pre-scale: (1/sqrt(64)) * log2(e)  -> softmax becomes exp2
#define SCALE_Q 0.1803368801111204f

// ---------------------------------------------------------------------------
// Scratch (__device__ globals; allocation-free rule)
// ---------------------------------------------------------------------------
__device__ __half g_x[S_LEN * D_MODEL];
__device__ __half g_a[S_LEN * D_MODEL];
__device__ __half g_q[S_LEN * D_MODEL];
__device__ __half g_k[S_LEN * D_MODEL];
__device__ __half g_v[S_LEN * D_MODEL];
__device__ __half g_wqkv[3 * D_MODEL * D_MODEL];   // rows: [Wq; Wk; Wv]
__device__ __half g_wo[D_MODEL * D_MODEL];

// ---------------------------------------------------------------------------
// Portable (sm_80+) tensor-core primitives, fp16
// ---------------------------------------------------------------------------
__device__ __forceinline__ uint32_t smem_u32(const void* p) {
    uint32_t a;
    asm("{ .reg .u64 t; cvta.to.shared.u64 t, %1; cvt.u32.u64 %0, t; }"
        : "=r"(a) : "l"(p));
    return a;
}

__device__ __forceinline__ void ldsm4(uint32_t* r, uint32_t addr) {
    asm volatile("ldmatrix.sync.aligned.m8n8.x4.shared.b16 {%0,%1,%2,%3}, [%4];"
        : "=r"(r[0]), "=r"(r[1]), "=r"(r[2]), "=r"(r[3]) : "r"(addr));
}

__device__ __forceinline__ void ldsm4t(uint32_t* r, uint32_t addr) {
    asm volatile("ldmatrix.sync.aligned.m8n8.x4.trans.shared.b16 {%0,%1,%2,%3}, [%4];"
        : "=r"(r[0]), "=r"(r[1]), "=r"(r[2]), "=r"(r[3]) : "r"(addr));
}

__device__ __forceinline__ void mma16816(float* d, const uint32_t* a, const uint32_t* b) {
    asm volatile(
        "mma.sync.aligned.m16n8k16.row.col.f32.f16.f16.f32 "
        "{%0,%1,%2,%3}, {%4,%5,%6,%7}, {%8,%9}, {%0,%1,%2,%3};"
        : "+f"(d[0]), "+f"(d[1]), "+f"(d[2]), "+f"(d[3])
        : "r"(a[0]), "r"(a[1]), "r"(a[2]), "r"(a[3]), "r"(b[0]), "r"(b[1]));
}

#define CP_ASYNC16(sa, ga) \
    asm volatile("cp.async.cg.shared.global [%0], [%1], 16;" :: "r"(sa), "l"(ga))
#define CP_COMMIT()  asm volatile("cp.async.commit_group;")
#define CP_WAIT(N)   asm volatile("cp.async.wait_group %0;" :: "n"(N))

#define EX2_F16X2(d, a) \
    asm volatile("ex2.approx.f16x2 %0, %1;" : "=r"(d) : "r"(a))

__device__ __forceinline__ uint32_t pack_h2(float a, float b) {
    __half2 hv; hv.x = __float2half_rn(a); hv.y = __float2half_rn(b);
    return *reinterpret_cast<uint32_t*>(&hv);
}

// ---------------------------------------------------------------------------
// One launch converts x, Wq, Wk, Wv, Wo -> fp16
// ---------------------------------------------------------------------------
__global__ void cvt_all(const float* __restrict__ x,
                        const float* __restrict__ Wq, const float* __restrict__ Wk,
                        const float* __restrict__ Wv, const float* __restrict__ Wo,
                        __half* __restrict__ xo, __half* __restrict__ wqkv,
                        __half* __restrict__ wo) {
    const int nx = S_LEN * D_MODEL;          // 4M
    const int nw = D_MODEL * D_MODEL;        // 1M
    int i = (blockIdx.x * blockDim.x + threadIdx.x) * 4;
    const float* src;
    __half* dst;
    int off;
    if (i < nx) { src = x; dst = xo; off = i; }
    else {
        int j = i - nx;
        int region = j / nw;                 // 0..3
        off = j - region * nw;
        src = (region == 0) ? Wq : (region == 1) ? Wk : (region == 2) ? Wv : Wo;
        dst = (region < 3) ? (wqkv + region * nw) : wo;
    }
    float4 v = *(const float4*)(src + off);
    *(uint32_t*)(dst + off)     = pack_h2(v.x, v.y);
    *(uint32_t*)(dst + off + 2) = pack_h2(v.z, v.w);
}

// ---------------------------------------------------------------------------
// fp16 GEMM via mma.sync: 128x128x32 tile, 256 threads, warps 2m x 4n.
// 3-stage cp.async pipeline.
// ---------------------------------------------------------------------------
#define GK       1024
#define BK       32
#define NKC      (GK / BK)
#define TILE8KB  8192
#define STAGE_B  (2 * TILE8KB)
#define GSMEM    (3 * STAGE_B)     // 48 KB, 3 stages

// -------- shared mainloop body (3-stage) --------
#define GEMM_MAINLOOP(A_PTR, B_PTR)                                            \
    const __half* srcs[2] = {A_PTR, B_PTR};                                    \
    auto load_stage = [&](int kt, int buf) {                                   \
        const int koff = kt * BK;                                              \
        char* sbase = sm + buf * STAGE_B;                                      \
        _Pragma("unroll")                                                      \
        for (int mtx = 0; mtx < 2; mtx++) {                                    \
            const __half* src = srcs[mtx];                                     \
            const int rbase = (mtx == 0) ? bm : bn;                            \
            char* stile = sbase + mtx * TILE8KB;                               \
            _Pragma("unroll")                                                  \
            for (int j = 0; j < 2; j++) {                                      \
                int qi  = tid + j * 256;                                       \
                int row = qi >> 2, q = qi & 3;                                 \
                int pq  = q ^ (row & 3);                                       \
                uint32_t sa = smem_u32(stile + row * 64 + pq * 16);            \
                const void* ga = src + (size_t)(rbase + row) * GK + koff + q * 8; \
                CP_ASYNC16(sa, ga);                                            \
            }                                                                  \
        }                                                                      \
    };                                                                         \
    float d[4][4][4];                                                          \
    _Pragma("unroll")                                                          \
    for (int i = 0; i < 4; i++)                                                \
        _Pragma("unroll")                                                      \
        for (int j = 0; j < 4; j++)                                            \
            _Pragma("unroll")                                                  \
            for (int k = 0; k < 4; k++) d[i][j][k] = 0.f;                      \
    load_stage(0, 0); CP_COMMIT();                                             \
    load_stage(1, 1); CP_COMMIT();                                             \
    const int a_row = lane & 15;                                               \
    const int a_qs  = lane >> 4;                                               \
    const int b_row = ((lane >> 4) & 1) * 8 + (lane & 7);                      \
    const int b_qs  = (lane >> 3) & 1;                                         \
    int cur = 0, nxt = 2;                                                      \
    for (int kt = 0; kt < NKC; kt++) {                                         \
        if (kt + 2 < NKC) {                                                    \
            load_stage(kt + 2, nxt); CP_COMMIT(); CP_WAIT(2);                  \
            nxt = (nxt == 2) ? 0 : nxt + 1;                                    \
        }                                                                      \
        else if (kt + 1 < NKC) { CP_WAIT(1); }                                 \
        else                   { CP_WAIT(0); }                                 \
        __syncthreads();                                                       \
        char* sbase = sm + cur * STAGE_B;                                      \
        cur = (cur == 2) ? 0 : cur + 1;                                        \
        char* tA = sbase;                                                      \
        char* tB = sbase + TILE8KB;                                            \
        _Pragma("unroll")                                                      \
        for (int ks = 0; ks < 2; ks++) {                                       \
            uint32_t af[4][4], bf[4][2];                                       \
            _Pragma("unroll")                                                  \
            for (int mi = 0; mi < 4; mi++) {                                   \
                int row = wm * 64 + mi * 16 + a_row;                           \
                int pq  = (ks * 2 + a_qs) ^ (row & 3);                         \
                ldsm4(af[mi], smem_u32(tA + row * 64 + pq * 16));              \
            }                                                                  \
            _Pragma("unroll")                                                  \
            for (int gi = 0; gi < 2; gi++) {                                   \
                int row = wn * 32 + gi * 16 + b_row;                           \
                int pq  = (ks * 2 + b_qs) ^ (row & 3);                         \
                uint32_t rh[4];                                                \
                ldsm4(rh, smem_u32(tB + row * 64 + pq * 16));                  \
                bf[gi * 2 + 0][0] = rh[0]; bf[gi * 2 + 0][1] = rh[1];          \
                bf[gi * 2 + 1][0] = rh[2]; bf[gi * 2 + 1][1] = rh[3];          \
            }                                                                  \
            _Pragma("unroll")                                                  \
            for (int mi = 0; mi < 4; mi++)                                     \
                _Pragma("unroll")                                              \
                for (int ni = 0; ni < 4; ni++)                                 \
                    mma16816(d[mi][ni], af[mi], bf[ni]);                       \
        }                                                                      \
        __syncthreads();                                                       \
    }

__global__ void __launch_bounds__(256, 2)
gemm_f16(const __half* __restrict__ A, const __half* __restrict__ B,
         float* __restrict__ C) {
    extern __shared__ char sm[];
    const int tid  = threadIdx.x;
    const int lane = tid & 31;
    const int warp = tid >> 5;
    const int wm   = warp & 1;
    const int wn   = warp >> 1;
    const int bm   = blockIdx.y * 128;
    const int bn   = blockIdx.x * 128;

    GEMM_MAINLOOP(A, B)

    const int er = lane >> 2;
    const int ec = (lane & 3) * 2;
    #pragma unroll
    for (int mi = 0; mi < 4; mi++) {
        int r0 = bm + wm * 64 + mi * 16 + er;
        #pragma unroll
        for (int ni = 0; ni < 4; ni++) {
            int c0 = bn + wn * 32 + ni * 8 + ec;
            *(float2*)(C + (size_t)r0 * D_MODEL + c0)       = make_float2(d[mi][ni][0], d[mi][ni][1]);
            *(float2*)(C + (size_t)(r0 + 8) * D_MODEL + c0) = make_float2(d[mi][ni][2], d[mi][ni][3]);
        }
    }
}

__global__ void __launch_bounds__(256, 2)
gemm_qkv(const __half* __restrict__ A, const __half* __restrict__ Bqkv,
         __half* __restrict__ Q, __half* __restrict__ K, __half* __restrict__ V,
         const int* __restrict__ pos) {
    extern __shared__ char sm[];
    const int tid  = threadIdx.x;
    const int lane = tid & 31;
    const int warp = tid >> 5;
    const int wm   = warp & 1;
    const int wn   = warp >> 1;
    const int bm   = blockIdx.y * 128;
    const int bn   = blockIdx.x * 128;       // 0..2944 within concat N=3072

    GEMM_MAINLOOP(A, Bqkv)

    const int er = lane >> 2;
    const int ec = (lane & 3) * 2;
    const int region = bn >> 10;             // 0=Q, 1=K, 2=V (CTA-uniform)
    __half* H = (region == 0) ? Q : (region == 1) ? K : V;

    #pragma unroll
    for (int ni = 0; ni < 4; ni++) {
        int c0g = bn + wn * 32 + ni * 8 + ec;
        int c0  = c0g & 1023;                // column within the region
        float finv = 0.f;
        if (region < 2) {
            int i = (c0 & (HDK - 1)) >> 1;
            finv = (float)exp(-(double)i * (1.0 / 32.0) * 9.210340371976184);
        }
        #pragma unroll
        for (int mi = 0; mi < 4; mi++) {
            int r0 = bm + wm * 64 + mi * 16 + er;
            #pragma unroll
            for (int half = 0; half < 2; half++) {
                int r = r0 + half * 8;
                float v0 = d[mi][ni][half * 2], v1 = d[mi][ni][half * 2 + 1];
                if (region < 2) {
                    float sn, cs;
                    sincosf((float)pos[r] * finv, &sn, &cs);
                    float e = v0 * cs - v1 * sn;
                    float o = v0 * sn + v1 * cs;
                    if (region == 0) { e *= SCALE_Q; o *= SCALE_Q; }
                    v0 = e; v1 = o;
                }
                *(uint32_t*)(H + (size_t)r * D_MODEL + c0) = pack_h2(v0, v1);
            }
        }
    }
}

// ---------------------------------------------------------------------------
// Flash attention (causal), mma.sync fp16, fp32 accum, exp2-domain softmax.
// Row-sums via ones-column MMA; exp via ex2.approx.f16x2; 3-stage kv ring.
// smem: Q (8KB) + 3 stages x {K,V} (16KB/stage) = 56KB; 4 CTAs/SM target.
// ---------------------------------------------------------------------------
#define QS_B      8192
#define AKV_B     (2 * QS_B)              // one {K,V} stage
#define ATT_SMEM  (QS_B + 3 * AKV_B)      // 56 KB

__global__ void __launch_bounds__(128, 4)
attn_mma(const __half* __restrict__ qg, const __half* __restrict__ kg,
         const __half* __restrict__ vg, __half* __restrict__ og) {
    extern __shared__ char sm[];
    const int tid  = threadIdx.x;
    const int lane = tid & 31;
    const int warp = tid >> 5;
    const int h    = blockIdx.y;
    const int qi   = gridDim.x - 1 - blockIdx.x;   // heavy tiles first
    const int q0   = qi * 64;
    const int ntiles = qi + 1;
    const int cbase  = h * HDK;

    char* Q_t = sm;

    #pragma unroll
    for (int j = 0; j < 4; j++) {
        int qq  = tid + j * 128;
        int row = qq >> 3, q = qq & 7;
        int pq  = q ^ (row & 7);
        CP_ASYNC16(smem_u32(Q_t + row * 128 + pq * 16),
                   qg + (size_t)(q0 + row) * D_MODEL + cbase + q * 8);
    }

    const __half* kvsrc[2] = {kg, vg};
    auto load_kv = [&](int jt, int buf) {
        int n0 = jt * 64;
        char* sb = sm + QS_B + buf * AKV_B;
        #pragma unroll
        for (int m = 0; m < 2; m++) {
            char* tile = sb + m * QS_B;
            #pragma unroll
            for (int j = 0; j < 4; j++) {
                int qq  = tid + j * 128;
                int row = qq >> 3, q = qq & 7;
                int pq  = q ^ (row & 7);
                CP_ASYNC16(smem_u32(tile + row * 128 + pq * 16),
                           kvsrc[m] + (size_t)(n0 + row) * D_MODEL + cbase + q * 8);
            }
        }
    };

    load_kv(0, 0);
    CP_COMMIT();
    if (ntiles > 1) { load_kv(1, 1); CP_COMMIT(); }

    float o[8][4];
    #pragma unroll
    for (int f = 0; f < 8; f++)
        #pragma unroll
        for (int k = 0; k < 4; k++) o[f][k] = 0.f;
    float m0 = -1e30f, m1 = -1e30f, l0 = 0.f, l1 = 0.f;
    const int g = lane >> 2;
    const uint32_t onesb[2] = {0x3C003C00u, 0x3C003C00u};   // half2(1,1) x2

    int cur = 0, nxt = 2;
    for (int jt = 0; jt < ntiles; jt++) {
        if (jt + 2 < ntiles) {
            load_kv(jt + 2, nxt); CP_COMMIT(); CP_WAIT(2);
            nxt = (nxt == 2) ? 0 : nxt + 1;
        }
        else if (jt + 1 < ntiles) { CP_WAIT(1); }
        else                      { CP_WAIT(0); }
        __syncthreads();

        char* sb  = sm + QS_B + cur * AKV_B;
        cur = (cur == 2) ? 0 : cur + 1;
        char* K_t = sb;
        char* V_t = sb + QS_B;

        // ---- S = Qs K^T (log2 domain); Q frags reloaded per tile ----
        float s[8][4];
        #pragma unroll
        for (int f = 0; f < 8; f++)
            #pragma unroll
            for (int k = 0; k < 4; k++) s[f][k] = 0.f;

        #pragma unroll
        for (int ks = 0; ks < 4; ks++) {
            uint32_t qf[4];
            {
                int row = warp * 16 + (lane & 15);
                int aq  = ks * 2 + (lane >> 4);
                int pq  = aq ^ (row & 7);
                ldsm4(qf, smem_u32(Q_t + row * 128 + pq * 16));
            }
            uint32_t rk[4][4];
            #pragma unroll
            for (int gi = 0; gi < 4; gi++) {
                int brow = gi * 16 + ((lane >> 4) & 1) * 8 + (lane & 7);
                int bq   = ks * 2 + ((lane >> 3) & 1);
                int pq   = bq ^ (brow & 7);
                ldsm4(rk[gi], smem_u32(K_t + brow * 128 + pq * 16));
            }
            #pragma unroll
            for (int gi = 0; gi < 4; gi++) {
                mma16816(s[gi * 2],     qf, rk[gi]);
                mma16816(s[gi * 2 + 1], qf, rk[gi] + 2);
            }
        }

        // ---- causal mask (diagonal tile only) ----
        if (jt == ntiles - 1) {
            int lr0 = warp * 16 + g, lr1 = lr0 + 8;
            #pragma unroll
            for (int f = 0; f < 8; f++) {
                int c0 = f * 8 + (lane & 3) * 2;
                if (c0     > lr0) s[f][0] = -1e30f;
                if (c0 + 1 > lr0) s[f][1] = -1e30f;
                if (c0     > lr1) s[f][2] = -1e30f;
                if (c0 + 1 > lr1) s[f][3] = -1e30f;
            }
        }

        // ---- running max (fp32) ----
        float mx0 = -1e30f, mx1 = -1e30f;
        #pragma unroll
        for (int f = 0; f < 8; f++) {
            mx0 = fmaxf(mx0, fmaxf(s[f][0], s[f][1]));
            mx1 = fmaxf(mx1, fmaxf(s[f][2], s[f][3]));
        }
        mx0 = fmaxf(mx0, __shfl_xor_sync(0xffffffffu, mx0, 1));
        mx0 = fmaxf(mx0, __shfl_xor_sync(0xffffffffu, mx0, 2));
        mx1 = fmaxf(mx1, __shfl_xor_sync(0xffffffffu, mx1, 1));
        mx1 = fmaxf(mx1, __shfl_xor_sync(0xffffffffu, mx1, 2));

        float mn0 = fmaxf(m0, mx0), mn1 = fmaxf(m1, mx1);
        float cr0 = exp2f(m0 - mn0), cr1 = exp2f(m1 - mn1);
        m0 = mn0; m1 = mn1;

        // ---- P = exp2(S - mn): fp32 subtract, then f16x2 ex2 (packed) ----
        uint32_t ph[16];
        #pragma unroll
        for (int f = 0; f < 8; f++) {
            uint32_t p0 = pack_h2(s[f][0] - mn0, s[f][1] - mn0);
            uint32_t p1 = pack_h2(s[f][2] - mn1, s[f][3] - mn1);
            EX2_F16X2(ph[2 * f],     p0);
            EX2_F16X2(ph[2 * f + 1], p1);
        }

        // ---- rescale O ----
        #pragma unroll
        for (int f = 0; f < 8; f++) {
            o[f][0] *= cr0; o[f][1] *= cr0;
            o[f][2] *= cr1; o[f][3] *= cr1;
        }

        // ---- O += P V; row-sums via ones-column MMA ----
        float lf[4] = {0.f, 0.f, 0.f, 0.f};
        #pragma unroll
        for (int ks2 = 0; ks2 < 4; ks2++) {
            const uint32_t* pa = &ph[4 * ks2];
            int vrow = ks2 * 16 + ((lane >> 3) & 1) * 8 + (lane & 7);
            uint32_t bv[4][4];
            #pragma unroll
            for (int nvp = 0; nvp < 4; nvp++) {
                int vq = nvp * 2 + (lane >> 4);
                int pq = vq ^ (vrow & 7);
                ldsm4t(bv[nvp], smem_u32(V_t + vrow * 128 + pq * 16));
            }
            #pragma unroll
            for (int nvp = 0; nvp < 4; nvp++) {
                mma16816(o[nvp * 2],     pa, bv[nvp]);
                mma16816(o[nvp * 2 + 1], pa, bv[nvp] + 2);
            }
            mma16816(lf, pa, onesb);
        }
        l0 = l0 * cr0 + lf[0];
        l1 = l1 * cr1 + lf[2];
        __syncthreads();
    }

    // ---- epilogue: normalize, store fp16 ----
    float inv0 = 1.f / l0, inv1 = 1.f / l1;
    int row0 = q0 + warp * 16 + g;
    int colb = cbase + (lane & 3) * 2;
    #pragma unroll
    for (int f = 0; f < 8; f++) {
        int c = colb + f * 8;
        *(uint32_t*)(og + (size_t)row0 * D_MODEL + c) =
            pack_h2(o[f][0] * inv0, o[f][1] * inv0);
        *(uint32_t*)(og + (size_t)(row0 + 8) * D_MODEL + c) =
            pack_h2(o[f][2] * inv1, o[f][3] * inv1);
    }
}

// ---------------------------------------------------------------------------
extern "C" void kernel_launch(void* const* d_in, const int* in_sizes, int n_in,
                              void* d_out, int out_size) {
    const float* x   = (const float*)d_in[0];
    const int*   pos = (const int*)d_in[1];
    const float* Wq  = (const float*)d_in[2];
    const float* Wk  = (const float*)d_in[3];
    const float* Wv  = (const float*)d_in[4];
    const float* Wo  = (const float*)d_in[5];
    float* out = (float*)d_out;

    __half *xp, *ap, *qp, *kp, *vp, *wqkv, *wo;
    cudaGetSymbolAddress((void**)&xp, g_x);
    cudaGetSymbolAddress((void**)&ap, g_a);
    cudaGetSymbolAddress((void**)&qp, g_q);
    cudaGetSymbolAddress((void**)&kp, g_k);
    cudaGetSymbolAddress((void**)&vp, g_v);
    cudaGetSymbolAddress((void**)&wqkv, g_wqkv);
    cudaGetSymbolAddress((void**)&wo, g_wo);

    cudaFuncSetAttribute(gemm_f16,  cudaFuncAttributeMaxDynamicSharedMemorySize, GSMEM);
    cudaFuncSetAttribute(gemm_qkv,  cudaFuncAttributeMaxDynamicSharedMemorySize, GSMEM);
    cudaFuncSetAttribute(attn_mma,  cudaFuncAttributeMaxDynamicSharedMemorySize, ATT_SMEM);

    const int nx = S_LEN * D_MODEL;
    const int nw = D_MODEL * D_MODEL;
    cvt_all<<<(nx + 4 * nw) / 1024, 256>>>(x, Wq, Wk, Wv, Wo, xp, wqkv, wo);

    dim3 gqkv(3 * D_MODEL / 128, S_LEN / 128);   // (24, 32) = 768 CTAs
    gemm_qkv<<<gqkv, 256, GSMEM>>>(xp, wqkv, qp, kp, vp, pos);

    dim3 gattn(S_LEN / 64, NHEAD);               // (64, 16)
    attn_mma<<<gattn, 128, ATT_SMEM>>>(qp, kp, vp, ap);

    dim3 gproj(D_MODEL / 128, S_LEN / 128);      // (8, 32)
    gemm_f16<<<gproj, 256, GSMEM>>>(ap, wo, out);
}

// round 17
// speedup vs baseline: 1.1722x; 1.1722x over previous
#include <cuda_runtime.h>
#include <cuda_fp16.h>
#include <stdint.h>
#include <math.h>

#define S_LEN 4096
#define D_MODEL 1024
#define NHEAD 16
#define HDK 64
// Q pre-scale: (1/sqrt(64)) * log2(e)  -> softmax becomes exp2
#define SCALE_Q 0.1803368801111204f

// ---------------------------------------------------------------------------
// Scratch (__device__ globals; allocation-free rule)
// ---------------------------------------------------------------------------
__device__ __half g_x[S_LEN * D_MODEL];
__device__ __half g_a[S_LEN * D_MODEL];
__device__ __half g_q[S_LEN * D_MODEL];
__device__ __half g_k[S_LEN * D_MODEL];
__device__ __half g_v[S_LEN * D_MODEL];
__device__ __half g_wqkv[3 * D_MODEL * D_MODEL];   // rows: [Wq; Wk; Wv]
__device__ __half g_wo[D_MODEL * D_MODEL];

// ---------------------------------------------------------------------------
// Portable (sm_80+) tensor-core primitives, fp16
// ---------------------------------------------------------------------------
__device__ __forceinline__ uint32_t smem_u32(const void* p) {
    uint32_t a;
    asm("{ .reg .u64 t; cvta.to.shared.u64 t, %1; cvt.u32.u64 %0, t; }"
        : "=r"(a) : "l"(p));
    return a;
}

__device__ __forceinline__ void ldsm4(uint32_t* r, uint32_t addr) {
    asm volatile("ldmatrix.sync.aligned.m8n8.x4.shared.b16 {%0,%1,%2,%3}, [%4];"
        : "=r"(r[0]), "=r"(r[1]), "=r"(r[2]), "=r"(r[3]) : "r"(addr));
}

__device__ __forceinline__ void ldsm4t(uint32_t* r, uint32_t addr) {
    asm volatile("ldmatrix.sync.aligned.m8n8.x4.trans.shared.b16 {%0,%1,%2,%3}, [%4];"
        : "=r"(r[0]), "=r"(r[1]), "=r"(r[2]), "=r"(r[3]) : "r"(addr));
}

__device__ __forceinline__ void mma16816(float* d, const uint32_t* a, const uint32_t* b) {
    asm volatile(
        "mma.sync.aligned.m16n8k16.row.col.f32.f16.f16.f32 "
        "{%0,%1,%2,%3}, {%4,%5,%6,%7}, {%8,%9}, {%0,%1,%2,%3};"
        : "+f"(d[0]), "+f"(d[1]), "+f"(d[2]), "+f"(d[3])
        : "r"(a[0]), "r"(a[1]), "r"(a[2]), "r"(a[3]), "r"(b[0]), "r"(b[1]));
}

#define CP_ASYNC16(sa, ga) \
    asm volatile("cp.async.cg.shared.global [%0], [%1], 16;" :: "r"(sa), "l"(ga))
#define CP_COMMIT()  asm volatile("cp.async.commit_group;")
#define CP_WAIT(N)   asm volatile("cp.async.wait_group %0;" :: "n"(N))

#define EX2_F16X2(d, a) \
    asm volatile("ex2.approx.f16x2 %0, %1;" : "=r"(d) : "r"(a))

__device__ __forceinline__ uint32_t pack_h2(float a, float b) {
    __half2 hv; hv.x = __float2half_rn(a); hv.y = __float2half_rn(b);
    return *reinterpret_cast<uint32_t*>(&hv);
}

// ---------------------------------------------------------------------------
// One launch converts x, Wq, Wk, Wv, Wo -> fp16
// ---------------------------------------------------------------------------
__global__ void cvt_all(const float* __restrict__ x,
                        const float* __restrict__ Wq, const float* __restrict__ Wk,
                        const float* __restrict__ Wv, const float* __restrict__ Wo,
                        __half* __restrict__ xo, __half* __restrict__ wqkv,
                        __half* __restrict__ wo) {
    const int nx = S_LEN * D_MODEL;          // 4M
    const int nw = D_MODEL * D_MODEL;        // 1M
    int i = (blockIdx.x * blockDim.x + threadIdx.x) * 4;
    const float* src;
    __half* dst;
    int off;
    if (i < nx) { src = x; dst = xo; off = i; }
    else {
        int j = i - nx;
        int region = j / nw;                 // 0..3
        off = j - region * nw;
        src = (region == 0) ? Wq : (region == 1) ? Wk : (region == 2) ? Wv : Wo;
        dst = (region < 3) ? (wqkv + region * nw) : wo;
    }
    float4 v = *(const float4*)(src + off);
    *(uint32_t*)(dst + off)     = pack_h2(v.x, v.y);
    *(uint32_t*)(dst + off + 2) = pack_h2(v.z, v.w);
}

// ---------------------------------------------------------------------------
// fp16 GEMM via mma.sync: 128x128x64 tile, 256 threads, warps 2m x 4n.
// BK=64 (16 iterations, half the barrier count), 2-stage cp.async.
// Tile rows are 128B; swizzle pq = q ^ (row & 7).
// ---------------------------------------------------------------------------
#define GK        1024
#define BK        64
#define NKC       (GK / BK)          // 16
#define TILE16KB  16384              // 128 rows x 128B
#define STAGE_B   (2 * TILE16KB)     // A + B = 32 KB
#define GSMEM     (2 * STAGE_B)      // 64 KB, 2 stages

// -------- shared mainloop body (BK=64, 2-stage) --------
#define GEMM_MAINLOOP(A_PTR, B_PTR)                                            \
    const __half* srcs[2] = {A_PTR, B_PTR};                                    \
    auto load_stage = [&](int kt, int buf) {                                   \
        const int koff = kt * BK;                                              \
        char* sbase = sm + buf * STAGE_B;                                      \
        _Pragma("unroll")                                                      \
        for (int mtx = 0; mtx < 2; mtx++) {                                    \
            const __half* src = srcs[mtx];                                     \
            const int rbase = (mtx == 0) ? bm : bn;                            \
            char* stile = sbase + mtx * TILE16KB;                              \
            _Pragma("unroll")                                                  \
            for (int j = 0; j < 4; j++) {                                      \
                int qi  = tid + j * 256;                                       \
                int row = qi >> 3, q = qi & 7;                                 \
                int pq  = q ^ (row & 7);                                       \
                uint32_t sa = smem_u32(stile + row * 128 + pq * 16);           \
                const void* ga = src + (size_t)(rbase + row) * GK + koff + q * 8; \
                CP_ASYNC16(sa, ga);                                            \
            }                                                                  \
        }                                                                      \
    };                                                                         \
    float d[4][4][4];                                                          \
    _Pragma("unroll")                                                          \
    for (int i = 0; i < 4; i++)                                                \
        _Pragma("unroll")                                                      \
        for (int j = 0; j < 4; j++)                                            \
            _Pragma("unroll")                                                  \
            for (int k = 0; k < 4; k++) d[i][j][k] = 0.f;                      \
    load_stage(0, 0);                                                          \
    CP_COMMIT();                                                               \
    const int a_row = lane & 15;                                               \
    const int a_qs  = lane >> 4;                                               \
    const int b_row = ((lane >> 4) & 1) * 8 + (lane & 7);                      \
    const int b_qs  = (lane >> 3) & 1;                                         \
    for (int kt = 0; kt < NKC; kt++) {                                         \
        if (kt + 1 < NKC) { load_stage(kt + 1, (kt + 1) & 1); CP_COMMIT(); CP_WAIT(1); } \
        else              { CP_WAIT(0); }                                      \
        __syncthreads();                                                       \
        char* sbase = sm + (kt & 1) * STAGE_B;                                 \
        char* tA = sbase;                                                      \
        char* tB = sbase + TILE16KB;                                           \
        _Pragma("unroll")                                                      \
        for (int ks = 0; ks < 4; ks++) {                                       \
            uint32_t af[4][4], bf[4][2];                                       \
            _Pragma("unroll")                                                  \
            for (int mi = 0; mi < 4; mi++) {                                   \
                int row = wm * 64 + mi * 16 + a_row;                           \
                int pq  = (ks * 2 + a_qs) ^ (row & 7);                         \
                ldsm4(af[mi], smem_u32(tA + row * 128 + pq * 16));             \
            }                                                                  \
            _Pragma("unroll")                                                  \
            for (int gi = 0; gi < 2; gi++) {                                   \
                int row = wn * 32 + gi * 16 + b_row;                           \
                int pq  = (ks * 2 + b_qs) ^ (row & 7);                         \
                uint32_t rh[4];                                                \
                ldsm4(rh, smem_u32(tB + row * 128 + pq * 16));                 \
                bf[gi * 2 + 0][0] = rh[0]; bf[gi * 2 + 0][1] = rh[1];          \
                bf[gi * 2 + 1][0] = rh[2]; bf[gi * 2 + 1][1] = rh[3];          \
            }                                                                  \
            _Pragma("unroll")                                                  \
            for (int mi = 0; mi < 4; mi++)                                     \
                _Pragma("unroll")                                              \
                for (int ni = 0; ni < 4; ni++)                                 \
                    mma16816(d[mi][ni], af[mi], bf[ni]);                       \
        }                                                                      \
        __syncthreads();                                                       \
    }

__global__ void __launch_bounds__(256, 2)
gemm_f16(const __half* __restrict__ A, const __half* __restrict__ B,
         float* __restrict__ C) {
    extern __shared__ char sm[];
    const int tid  = threadIdx.x;
    const int lane = tid & 31;
    const int warp = tid >> 5;
    const int wm   = warp & 1;
    const int wn   = warp >> 1;
    const int bm   = blockIdx.y * 128;
    const int bn   = blockIdx.x * 128;

    GEMM_MAINLOOP(A, B)

    const int er = lane >> 2;
    const int ec = (lane & 3) * 2;
    #pragma unroll
    for (int mi = 0; mi < 4; mi++) {
        int r0 = bm + wm * 64 + mi * 16 + er;
        #pragma unroll
        for (int ni = 0; ni < 4; ni++) {
            int c0 = bn + wn * 32 + ni * 8 + ec;
            *(float2*)(C + (size_t)r0 * D_MODEL + c0)       = make_float2(d[mi][ni][0], d[mi][ni][1]);
            *(float2*)(C + (size_t)(r0 + 8) * D_MODEL + c0) = make_float2(d[mi][ni][2], d[mi][ni][3]);
        }
    }
}

__global__ void __launch_bounds__(256, 2)
gemm_qkv(const __half* __restrict__ A, const __half* __restrict__ Bqkv,
         __half* __restrict__ Q, __half* __restrict__ K, __half* __restrict__ V,
         const int* __restrict__ pos) {
    extern __shared__ char sm[];
    const int tid  = threadIdx.x;
    const int lane = tid & 31;
    const int warp = tid >> 5;
    const int wm   = warp & 1;
    const int wn   = warp >> 1;
    const int bm   = blockIdx.y * 128;
    const int bn   = blockIdx.x * 128;       // 0..2944 within concat N=3072

    GEMM_MAINLOOP(A, Bqkv)

    const int er = lane >> 2;
    const int ec = (lane & 3) * 2;
    const int region = bn >> 10;             // 0=Q, 1=K, 2=V (CTA-uniform)
    __half* H = (region == 0) ? Q : (region == 1) ? K : V;

    #pragma unroll
    for (int ni = 0; ni < 4; ni++) {
        int c0g = bn + wn * 32 + ni * 8 + ec;
        int c0  = c0g & 1023;                // column within the region
        float finv = 0.f;
        if (region < 2) {
            int i = (c0 & (HDK - 1)) >> 1;
            finv = (float)exp(-(double)i * (1.0 / 32.0) * 9.210340371976184);
        }
        #pragma unroll
        for (int mi = 0; mi < 4; mi++) {
            int r0 = bm + wm * 64 + mi * 16 + er;
            #pragma unroll
            for (int half = 0; half < 2; half++) {
                int r = r0 + half * 8;
                float v0 = d[mi][ni][half * 2], v1 = d[mi][ni][half * 2 + 1];
                if (region < 2) {
                    float sn, cs;
                    sincosf((float)pos[r] * finv, &sn, &cs);
                    float e = v0 * cs - v1 * sn;
                    float o = v0 * sn + v1 * cs;
                    if (region == 0) { e *= SCALE_Q; o *= SCALE_Q; }
                    v0 = e; v1 = o;
                }
                *(uint32_t*)(H + (size_t)r * D_MODEL + c0) = pack_h2(v0, v1);
            }
        }
    }
}

// ---------------------------------------------------------------------------
// Flash attention (causal), mma.sync fp16, fp32 accum, exp2-domain softmax.
// Row-sums via ones-column MMA; exp via ex2.approx.f16x2; Q frags reloaded
// per tile. 2-stage kv ring (R14 config — 3-stage regressed).
// smem: Q (8KB) + 2 stages x {K,V} (16KB/stage) = 40KB; 4 CTAs/SM target.
// ---------------------------------------------------------------------------
#define QS_B      8192
#define ASTAGE_B  (2 * QS_B)
#define ATT_SMEM  (QS_B + 2 * ASTAGE_B)

__global__ void __launch_bounds__(128, 4)
attn_mma(const __half* __restrict__ qg, const __half* __restrict__ kg,
         const __half* __restrict__ vg, __half* __restrict__ og) {
    extern __shared__ char sm[];
    const int tid  = threadIdx.x;
    const int lane = tid & 31;
    const int warp = tid >> 5;
    const int h    = blockIdx.y;
    const int qi   = gridDim.x - 1 - blockIdx.x;   // heavy tiles first
    const int q0   = qi * 64;
    const int ntiles = qi + 1;
    const int cbase  = h * HDK;

    char* Q_t = sm;

    #pragma unroll
    for (int j = 0; j < 4; j++) {
        int qq  = tid + j * 128;
        int row = qq >> 3, q = qq & 7;
        int pq  = q ^ (row & 7);
        CP_ASYNC16(smem_u32(Q_t + row * 128 + pq * 16),
                   qg + (size_t)(q0 + row) * D_MODEL + cbase + q * 8);
    }

    const __half* kvsrc[2] = {kg, vg};
    auto load_kv = [&](int jt, int buf) {
        int n0 = jt * 64;
        char* sb = sm + QS_B + buf * ASTAGE_B;
        #pragma unroll
        for (int m = 0; m < 2; m++) {
            char* tile = sb + m * QS_B;
            #pragma unroll
            for (int j = 0; j < 4; j++) {
                int qq  = tid + j * 128;
                int row = qq >> 3, q = qq & 7;
                int pq  = q ^ (row & 7);
                CP_ASYNC16(smem_u32(tile + row * 128 + pq * 16),
                           kvsrc[m] + (size_t)(n0 + row) * D_MODEL + cbase + q * 8);
            }
        }
    };

    load_kv(0, 0);
    CP_COMMIT();

    float o[8][4];
    #pragma unroll
    for (int f = 0; f < 8; f++)
        #pragma unroll
        for (int k = 0; k < 4; k++) o[f][k] = 0.f;
    float m0 = -1e30f, m1 = -1e30f, l0 = 0.f, l1 = 0.f;
    const int g = lane >> 2;
    const uint32_t onesb[2] = {0x3C003C00u, 0x3C003C00u};   // half2(1,1) x2

    for (int jt = 0; jt < ntiles; jt++) {
        if (jt + 1 < ntiles) { load_kv(jt + 1, (jt + 1) & 1); CP_COMMIT(); CP_WAIT(1); }
        else                 { CP_WAIT(0); }
        __syncthreads();

        char* sb  = sm + QS_B + (jt & 1) * ASTAGE_B;
        char* K_t = sb;
        char* V_t = sb + QS_B;

        // ---- S = Qs K^T (log2 domain); Q frags reloaded per tile ----
        float s[8][4];
        #pragma unroll
        for (int f = 0; f < 8; f++)
            #pragma unroll
            for (int k = 0; k < 4; k++) s[f][k] = 0.f;

        #pragma unroll
        for (int ks = 0; ks < 4; ks++) {
            uint32_t qf[4];
            {
                int row = warp * 16 + (lane & 15);
                int aq  = ks * 2 + (lane >> 4);
                int pq  = aq ^ (row & 7);
                ldsm4(qf, smem_u32(Q_t + row * 128 + pq * 16));
            }
            uint32_t rk[4][4];
            #pragma unroll
            for (int gi = 0; gi < 4; gi++) {
                int brow = gi * 16 + ((lane >> 4) & 1) * 8 + (lane & 7);
                int bq   = ks * 2 + ((lane >> 3) & 1);
                int pq   = bq ^ (brow & 7);
                ldsm4(rk[gi], smem_u32(K_t + brow * 128 + pq * 16));
            }
            #pragma unroll
            for (int gi = 0; gi < 4; gi++) {
                mma16816(s[gi * 2],     qf, rk[gi]);
                mma16816(s[gi * 2 + 1], qf, rk[gi] + 2);
            }
        }

        // ---- causal mask (diagonal tile only) ----
        if (jt == ntiles - 1) {
            int lr0 = warp * 16 + g, lr1 = lr0 + 8;
            #pragma unroll
            for (int f = 0; f < 8; f++) {
                int c0 = f * 8 + (lane & 3) * 2;
                if (c0     > lr0) s[f][0] = -1e30f;
                if (c0 + 1 > lr0) s[f][1] = -1e30f;
                if (c0     > lr1) s[f][2] = -1e30f;
                if (c0 + 1 > lr1) s[f][3] = -1e30f;
            }
        }

        // ---- running max (fp32) ----
        float mx0 = -1e30f, mx1 = -1e30f;
        #pragma unroll
        for (int f = 0; f < 8; f++) {
            mx0 = fmaxf(mx0, fmaxf(s[f][0], s[f][1]));
            mx1 = fmaxf(mx1, fmaxf(s[f][2], s[f][3]));
        }
        mx0 = fmaxf(mx0, __shfl_xor_sync(0xffffffffu, mx0, 1));
        mx0 = fmaxf(mx0, __shfl_xor_sync(0xffffffffu, mx0, 2));
        mx1 = fmaxf(mx1, __shfl_xor_sync(0xffffffffu, mx1, 1));
        mx1 = fmaxf(mx1, __shfl_xor_sync(0xffffffffu, mx1, 2));

        float mn0 = fmaxf(m0, mx0), mn1 = fmaxf(m1, mx1);
        float cr0 = exp2f(m0 - mn0), cr1 = exp2f(m1 - mn1);
        m0 = mn0; m1 = mn1;

        // ---- P = exp2(S - mn): fp32 subtract, then f16x2 ex2 (packed) ----
        uint32_t ph[16];
        #pragma unroll
        for (int f = 0; f < 8; f++) {
            uint32_t p0 = pack_h2(s[f][0] - mn0, s[f][1] - mn0);
            uint32_t p1 = pack_h2(s[f][2] - mn1, s[f][3] - mn1);
            EX2_F16X2(ph[2 * f],     p0);
            EX2_F16X2(ph[2 * f + 1], p1);
        }

        // ---- rescale O ----
        #pragma unroll
        for (int f = 0; f < 8; f++) {
            o[f][0] *= cr0; o[f][1] *= cr0;
            o[f][2] *= cr1; o[f][3] *= cr1;
        }

        // ---- O += P V; row-sums via ones-column MMA ----
        float lf[4] = {0.f, 0.f, 0.f, 0.f};
        #pragma unroll
        for (int ks2 = 0; ks2 < 4; ks2++) {
            const uint32_t* pa = &ph[4 * ks2];
            int vrow = ks2 * 16 + ((lane >> 3) & 1) * 8 + (lane & 7);
            uint32_t bv[4][4];
            #pragma unroll
            for (int nvp = 0; nvp < 4; nvp++) {
                int vq = nvp * 2 + (lane >> 4);
                int pq = vq ^ (vrow & 7);
                ldsm4t(bv[nvp], smem_u32(V_t + vrow * 128 + pq * 16));
            }
            #pragma unroll
            for (int nvp = 0; nvp < 4; nvp++) {
                mma16816(o[nvp * 2],     pa, bv[nvp]);
                mma16816(o[nvp * 2 + 1], pa, bv[nvp] + 2);
            }
            mma16816(lf, pa, onesb);
        }
        l0 = l0 * cr0 + lf[0];
        l1 = l1 * cr1 + lf[2];
        __syncthreads();
    }

    // ---- epilogue: normalize, store fp16 ----
    float inv0 = 1.f / l0, inv1 = 1.f / l1;
    int row0 = q0 + warp * 16 + g;
    int colb = cbase + (lane & 3) * 2;
    #pragma unroll
    for (int f = 0; f < 8; f++) {
        int c = colb + f * 8;
        *(uint32_t*)(og + (size_t)row0 * D_MODEL + c) =
            pack_h2(o[f][0] * inv0, o[f][1] * inv0);
        *(uint32_t*)(og + (size_t)(row0 + 8) * D_MODEL + c) =
            pack_h2(o[f][2] * inv1, o[f][3] * inv1);
    }
}

// ---------------------------------------------------------------------------
extern "C" void kernel_launch(void* const* d_in, const int* in_sizes, int n_in,
                              void* d_out, int out_size) {
    const float* x   = (const float*)d_in[0];
    const int*   pos = (const int*)d_in[1];
    const float* Wq  = (const float*)d_in[2];
    const float* Wk  = (const float*)d_in[3];
    const float* Wv  = (const float*)d_in[4];
    const float* Wo  = (const float*)d_in[5];
    float* out = (float*)d_out;

    __half *xp, *ap, *qp, *kp, *vp, *wqkv, *wo;
    cudaGetSymbolAddress((void**)&xp, g_x);
    cudaGetSymbolAddress((void**)&ap, g_a);
    cudaGetSymbolAddress((void**)&qp, g_q);
    cudaGetSymbolAddress((void**)&kp, g_k);
    cudaGetSymbolAddress((void**)&vp, g_v);
    cudaGetSymbolAddress((void**)&wqkv, g_wqkv);
    cudaGetSymbolAddress((void**)&wo, g_wo);

    cudaFuncSetAttribute(gemm_f16,  cudaFuncAttributeMaxDynamicSharedMemorySize, GSMEM);
    cudaFuncSetAttribute(gemm_qkv,  cudaFuncAttributeMaxDynamicSharedMemorySize, GSMEM);
    cudaFuncSetAttribute(attn_mma,  cudaFuncAttributeMaxDynamicSharedMemorySize, ATT_SMEM);

    const int nx = S_LEN * D_MODEL;
    const int nw = D_MODEL * D_MODEL;
    cvt_all<<<(nx + 4 * nw) / 1024, 256>>>(x, Wq, Wk, Wv, Wo, xp, wqkv, wo);

    dim3 gqkv(3 * D_MODEL / 128, S_LEN / 128);   // (24, 32) = 768 CTAs
    gemm_qkv<<<gqkv, 256, GSMEM>>>(xp, wqkv, qp, kp, vp, pos);

    dim3 gattn(S_LEN / 64, NHEAD);               // (64, 16)
    attn_mma<<<gattn, 128, ATT_SMEM>>>(qp, kp, vp, ap);

    dim3 gproj(D_MODEL / 128, S_LEN / 128);      // (8, 32)
    gemm_f16<<<gproj, 256, GSMEM>>>(ap, wo, out);
}